// round 13
// baseline (speedup 1.0000x reference)
#include <cuda_runtime.h>
#include <cstdint>

// FusionFeature_Layer on GB300 — emulated-fp32 flash attention on mma.sync
// (bf16 hi/lo 3-term split), bf16 prepass + cp.async pipelined tiles,
// now with 3-way m-split + fused in-kernel combine (counter handoff).
//
//   qf[b,n,c] = query.flat [b*N*C + n*C + c]
//   sf[b,c,m] = support.flat[b*C*N + c*N + m]
//   A = qf @ sf ; attn = softmax(A) ; mask = sigmoid(rowsum(A))
//   out_q = q + (attn @ qf) * mask ;  out_s = s * (1 + mask)
// No max-subtraction => partial (O, rawsum, expsum) over m-ranges simply add.

namespace {
constexpr int kB = 8, kC = 128, kN = 3136;   // N = 56*56 = 98*32
constexpr int TM = 64, TN = 32, NTH = 128;
constexpr int NUM_MT = kN / TN;              // 98
constexpr int NSPLIT = 3;                    // m-split: 33/33/32 tiles
constexpr int BUF_BYTES = 32768;             // S(16K) + V 4x4K regions
constexpr int OFF_ROW   = 3 * BUF_BYTES;     // float rowmask1[64]
constexpr int OFF_FLAG  = OFF_ROW + 240;     // int finisher flag
constexpr int SMEM_BYTES = OFF_ROW + 256;
constexpr size_t SZ = (size_t)kB * kN * kC;
}

// bf16 hi/lo scratch (prepass) + split-m partials + tile counters
__device__ __align__(16) uint16_t g_qh[SZ];
__device__ __align__(16) uint16_t g_ql[SZ];
__device__ __align__(16) uint16_t g_sh[SZ];
__device__ __align__(16) uint16_t g_sl[SZ];
__device__ __align__(16) float    g_osc[NSPLIT][SZ];
__device__ float g_rsc[NSPLIT][kB * kN];
__device__ float g_esc[NSPLIT][kB * kN];
__device__ unsigned int g_cnt[49 * kB];      // self-resetting

#define SWZ(b) ((b) ^ (((b) >> 3) & 0x70))

__device__ __forceinline__ uint32_t smem_to_u32(const void* p) {
    uint32_t a;
    asm("{ .reg .u64 t; cvta.to.shared.u64 t, %1; cvt.u32.u64 %0, t; }" : "=r"(a) : "l"(p));
    return a;
}
__device__ __forceinline__ void cp16(uint32_t dst, const void* src) {
    asm volatile("cp.async.cg.shared.global [%0], [%1], 16;" :: "r"(dst), "l"(src));
}
#define CP_COMMIT() asm volatile("cp.async.commit_group;" ::: "memory")
#define CP_WAIT0()  asm volatile("cp.async.wait_group 0;" ::: "memory")
#define CP_WAIT1()  asm volatile("cp.async.wait_group 1;" ::: "memory")

__device__ __forceinline__ void ldsm_x4(uint32_t r[4], uint32_t addr) {
    asm volatile("ldmatrix.sync.aligned.m8n8.x4.shared.b16 {%0,%1,%2,%3}, [%4];"
                 : "=r"(r[0]), "=r"(r[1]), "=r"(r[2]), "=r"(r[3]) : "r"(addr));
}
__device__ __forceinline__ void ldsm_x4_t(uint32_t r[4], uint32_t addr) {
    asm volatile("ldmatrix.sync.aligned.m8n8.x4.trans.shared.b16 {%0,%1,%2,%3}, [%4];"
                 : "=r"(r[0]), "=r"(r[1]), "=r"(r[2]), "=r"(r[3]) : "r"(addr));
}
__device__ __forceinline__ void mma_bf16(float (&d)[4], const uint32_t (&a)[4],
                                         uint32_t b0, uint32_t b1) {
    asm volatile("mma.sync.aligned.m16n8k16.row.col.f32.bf16.bf16.f32 "
                 "{%0,%1,%2,%3}, {%4,%5,%6,%7}, {%8,%9}, {%0,%1,%2,%3};"
                 : "+f"(d[0]), "+f"(d[1]), "+f"(d[2]), "+f"(d[3])
                 : "r"(a[0]), "r"(a[1]), "r"(a[2]), "r"(a[3]), "r"(b0), "r"(b1));
}
__device__ __forceinline__ void split2(float x, float y, uint32_t& hi, uint32_t& lo) {
    asm("cvt.rn.satfinite.bf16x2.f32 %0, %1, %2;" : "=r"(hi) : "f"(y), "f"(x));
    float rx = x - __uint_as_float(hi << 16);
    float ry = y - __uint_as_float(hi & 0xFFFF0000u);
    asm("cvt.rn.satfinite.bf16x2.f32 %0, %1, %2;" : "=r"(lo) : "f"(ry), "f"(rx));
}

// ---------------------------------------------------------------------------
__global__ __launch_bounds__(256)
void prepass_kernel(const float* __restrict__ q, const float* __restrict__ s)
{
    const size_t nf4 = SZ / 4;
    size_t i = (size_t)blockIdx.x * blockDim.x + threadIdx.x;
    const float* src;
    uint16_t *dh, *dl;
    size_t idx;
    if (i < nf4) { src = q; dh = g_qh; dl = g_ql; idx = i; }
    else         { src = s; dh = g_sh; dl = g_sl; idx = i - nf4; }
    float4 v = reinterpret_cast<const float4*>(src)[idx];
    uint32_t h0, l0, h1, l1;
    split2(v.x, v.y, h0, l0);
    split2(v.z, v.w, h1, l1);
    reinterpret_cast<uint2*>(dh)[idx] = make_uint2(h0, h1);
    reinterpret_cast<uint2*>(dl)[idx] = make_uint2(l0, l1);
}

// ---------------------------------------------------------------------------
__device__ __forceinline__ void load_tile(uint32_t bb, int tid, int b, int m0)
{
    #pragma unroll
    for (int i = 0; i < 8; i++) {                     // S: [128 c][hi64B|lo64B]
        int idx = tid + i * NTH;
        int c = idx >> 3, j = idx & 7;
        int jj = j & 3;
        const uint16_t* src = (j < 4 ? g_sh : g_sl)
            + ((size_t)(b * kC + c) * kN + m0 + jj * 8);
        uint32_t dst = bb + SWZ((uint32_t)(c * 128 + ((j >> 2) << 6) + jj * 16));
        cp16(dst, src);
    }
    #pragma unroll
    for (int i = 0; i < 8; i++) {                     // V: 4 regions [32][128B]
        int idx = tid + i * NTH;
        int rg = idx >> 8, m = (idx >> 3) & 31, j = idx & 7;
        const uint16_t* base = (rg < 2 ? g_qh : g_ql);
        const uint16_t* src = base + ((size_t)(b * kN + m0 + m) * kC) + (rg & 1) * 64 + j * 8;
        uint32_t dst = bb + 16384 + (uint32_t)rg * 4096 + SWZ((uint32_t)(m * 128 + j * 16));
        cp16(dst, src);
    }
}

__global__ __launch_bounds__(NTH, 2)
void fusion_mma_kernel(const float* __restrict__ q,
                       const float* __restrict__ s,
                       float* __restrict__ out)
{
    extern __shared__ char smem[];
    const uint32_t sb = smem_to_u32(smem);
    float* rowbuf = reinterpret_cast<float*>(smem + OFF_ROW);
    int*   sflag  = reinterpret_cast<int*>(smem + OFF_FLAG);

    const int tid  = threadIdx.x;
    const int lane = tid & 31;
    const int wid  = tid >> 5;
    const int R    = wid * 16;
    const int rowA = lane & 15;
    const int gcol = (lane >> 4) << 4;

    const int b  = blockIdx.y;
    const int n0 = blockIdx.x * TM;
    const int z  = blockIdx.z;
    const int mtb = z * 33;
    const int mte = (z == NSPLIT - 1) ? NUM_MT : mtb + 33;
    const float* __restrict__ qb  = q + (size_t)b * kN * kC;
    const float* __restrict__ sbp = s + (size_t)b * kN * kC;

    // ---- Stage Q tile, hoist A-fragments ----
    #pragma unroll
    for (int i = 0; i < 16; i++) {
        int idx = tid + i * NTH;
        int hl = idx >> 10;
        int r = (idx >> 4) & 63, j = idx & 15;
        int ch = j >> 3, jj = j & 7;
        const uint16_t* base = hl ? g_ql : g_qh;
        const uint16_t* src = base + ((size_t)(b * kN + n0 + r) * kC) + ch * 64 + jj * 8;
        uint32_t dst = sb + (uint32_t)hl * 16384 + (uint32_t)ch * 8192
                     + SWZ((uint32_t)(r * 128 + jj * 16));
        cp16(dst, src);
    }
    CP_COMMIT(); CP_WAIT0(); __syncthreads();

    uint32_t qah[8][4], qal[8][4];
    #pragma unroll
    for (int k = 0; k < 8; k++) {
        uint32_t inner = SWZ((uint32_t)((R + rowA) * 128 + ((k & 3) << 5) + gcol));
        ldsm_x4(qah[k], sb + ((uint32_t)(k >> 2) << 13) + inner);
        ldsm_x4(qal[k], sb + 16384 + ((uint32_t)(k >> 2) << 13) + inner);
    }
    __syncthreads();

    float oacc[16][4];
    #pragma unroll
    for (int i = 0; i < 16; i++)
        #pragma unroll
        for (int j = 0; j < 4; j++) oacc[i][j] = 0.f;
    float raw0 = 0.f, raw1 = 0.f, es0 = 0.f, es1 = 0.f;

    load_tile(sb,             tid, b, mtb * TN);       CP_COMMIT();
    load_tile(sb + BUF_BYTES, tid, b, (mtb + 1) * TN); CP_COMMIT();

    uint32_t bufc = sb;
    uint32_t bufp = sb + 2u * BUF_BYTES;

    #pragma unroll 1
    for (int mt = mtb; mt < mte; mt++) {
        CP_WAIT1();
        __syncthreads();
        if (mt + 2 < mte) load_tile(bufp, tid, b, (mt + 2) * TN);
        CP_COMMIT();

        const uint32_t bb = bufc;

        // ---- GEMM1: S(16x32/warp) = Q(16x128) @ Sf(128x32), 3-term ----
        float sacc[4][4];
        #pragma unroll
        for (int i = 0; i < 4; i++)
            #pragma unroll
            for (int j = 0; j < 4; j++) sacc[i][j] = 0.f;

        #pragma unroll
        for (int k = 0; k < 8; k++) {
            uint32_t rowb = (uint32_t)((k * 16 + rowA) * 128);
            #pragma unroll
            for (int np = 0; np < 2; np++) {
                uint32_t bh[4], bl[4];
                ldsm_x4_t(bh, bb + SWZ(rowb + ((uint32_t)np << 5) + gcol));
                ldsm_x4_t(bl, bb + SWZ(rowb + 64 + ((uint32_t)np << 5) + gcol));
                mma_bf16(sacc[2*np],   qah[k], bh[0], bh[1]);
                mma_bf16(sacc[2*np],   qah[k], bl[0], bl[1]);
                mma_bf16(sacc[2*np],   qal[k], bh[0], bh[1]);
                mma_bf16(sacc[2*np+1], qah[k], bh[2], bh[3]);
                mma_bf16(sacc[2*np+1], qah[k], bl[2], bl[3]);
                mma_bf16(sacc[2*np+1], qal[k], bh[2], bh[3]);
            }
        }

        // ---- exp + partials; pack P into GEMM2 A-fragments ----
        uint32_t pah[2][4], pal[2][4];
        #pragma unroll
        for (int nt = 0; nt < 4; nt++) {
            float v0 = sacc[nt][0], v1 = sacc[nt][1], v2 = sacc[nt][2], v3 = sacc[nt][3];
            raw0 += v0 + v1;  raw1 += v2 + v3;
            float e0 = __expf(v0), e1 = __expf(v1), e2 = __expf(v2), e3 = __expf(v3);
            es0 += e0 + e1;   es1 += e2 + e3;
            int kt = nt >> 1, o = (nt & 1) << 1;
            split2(e0, e1, pah[kt][o],     pal[kt][o]);
            split2(e2, e3, pah[kt][o + 1], pal[kt][o + 1]);
        }

        // ---- GEMM2: O(16x128/warp) += P(16x32) @ V(32x128), 3-term ----
        #pragma unroll
        for (int np = 0; np < 8; np++) {
            uint32_t vb = bb + 16384 + (((uint32_t)np >> 2) << 12);
            #pragma unroll
            for (int kt = 0; kt < 2; kt++) {
                uint32_t bh[4], bl[4];
                uint32_t off = SWZ((uint32_t)((kt * 16 + rowA) * 128 + ((np & 3) << 5) + gcol));
                ldsm_x4_t(bh, vb + off);
                ldsm_x4_t(bl, vb + 8192 + off);
                mma_bf16(oacc[2*np],   pah[kt], bh[0], bh[1]);
                mma_bf16(oacc[2*np],   pah[kt], bl[0], bl[1]);
                mma_bf16(oacc[2*np],   pal[kt], bh[0], bh[1]);
                mma_bf16(oacc[2*np+1], pah[kt], bh[2], bh[3]);
                mma_bf16(oacc[2*np+1], pah[kt], bl[2], bl[3]);
                mma_bf16(oacc[2*np+1], pal[kt], bh[2], bh[3]);
            }
        }

        bufc = (bufc == sb + 2u * BUF_BYTES) ? sb : bufc + BUF_BYTES;
        bufp = (bufp == sb + 2u * BUF_BYTES) ? sb : bufp + BUF_BYTES;
    }

    // ---- quad-reduce row partials (rows gr0 = lane/4, gr1 = gr0+8) ----
    #pragma unroll
    for (int off = 1; off < 4; off <<= 1) {
        raw0 += __shfl_xor_sync(0xffffffffu, raw0, off);
        raw1 += __shfl_xor_sync(0xffffffffu, raw1, off);
        es0  += __shfl_xor_sync(0xffffffffu, es0,  off);
        es1  += __shfl_xor_sync(0xffffffffu, es1,  off);
    }

    const int gr0 = n0 + R + (lane >> 2);
    const int gr1 = gr0 + 8;
    const size_t gb0 = (size_t)b * kN + gr0;
    const size_t gb1 = (size_t)b * kN + gr1;

    // ---- publish partials ----
    if ((lane & 3) == 0) {
        g_rsc[z][gb0] = raw0;  g_esc[z][gb0] = es0;
        g_rsc[z][gb1] = raw1;  g_esc[z][gb1] = es1;
    }
    {
        float* op = g_osc[z];
        #pragma unroll
        for (int nt = 0; nt < 16; nt++) {
            int c = nt * 8 + (lane & 3) * 2;
            *reinterpret_cast<float2*>(op + gb0 * kC + c) = make_float2(oacc[nt][0], oacc[nt][1]);
            *reinterpret_cast<float2*>(op + gb1 * kC + c) = make_float2(oacc[nt][2], oacc[nt][3]);
        }
    }
    __syncthreads();
    if (tid == 0) {
        __threadfence();                               // release partials
        unsigned old = atomicAdd(&g_cnt[b * 49 + blockIdx.x], 1u);
        *sflag = (old == NSPLIT - 1);
        if (old == NSPLIT - 1) {
            g_cnt[b * 49 + blockIdx.x] = 0;            // reset for next replay
            __threadfence();                           // acquire other partials
        }
    }
    __syncthreads();
    if (!*sflag) return;

    // ---- finisher: combine partials, normalize, write outputs ----
    const int z1 = (z + 1) % NSPLIT, z2 = (z + 2) % NSPLIT;
    float rs0 = raw0 + g_rsc[z1][gb0] + g_rsc[z2][gb0];
    float rs1 = raw1 + g_rsc[z1][gb1] + g_rsc[z2][gb1];
    float et0 = es0  + g_esc[z1][gb0] + g_esc[z2][gb0];
    float et1 = es1  + g_esc[z1][gb1] + g_esc[z2][gb1];
    float mask0 = 1.f / (1.f + __expf(-rs0));
    float mask1 = 1.f / (1.f + __expf(-rs1));
    float sc0 = mask0 / et0, sc1 = mask1 / et1;
    if ((lane & 3) == 0) {
        rowbuf[R + (lane >> 2)]     = 1.f + mask0;
        rowbuf[R + (lane >> 2) + 8] = 1.f + mask1;
    }

    {
        float* outq = out + (size_t)b * kN * kC;
        const float* p1 = g_osc[z1];
        const float* p2 = g_osc[z2];
        #pragma unroll
        for (int nt = 0; nt < 16; nt++) {
            int c = nt * 8 + (lane & 3) * 2;
            float2 a1 = *reinterpret_cast<const float2*>(p1 + gb0 * kC + c);
            float2 a2 = *reinterpret_cast<const float2*>(p2 + gb0 * kC + c);
            float2 b1 = *reinterpret_cast<const float2*>(p1 + gb1 * kC + c);
            float2 b2 = *reinterpret_cast<const float2*>(p2 + gb1 * kC + c);
            float2 q0 = *reinterpret_cast<const float2*>(qb + (size_t)gr0 * kC + c);
            float2 q1 = *reinterpret_cast<const float2*>(qb + (size_t)gr1 * kC + c);
            float2 o0, o1;
            o0.x = fmaf(oacc[nt][0] + a1.x + a2.x, sc0, q0.x);
            o0.y = fmaf(oacc[nt][1] + a1.y + a2.y, sc0, q0.y);
            o1.x = fmaf(oacc[nt][2] + b1.x + b2.x, sc1, q1.x);
            o1.y = fmaf(oacc[nt][3] + b1.y + b2.y, sc1, q1.y);
            *reinterpret_cast<float2*>(outq + (size_t)gr0 * kC + c) = o0;
            *reinterpret_cast<float2*>(outq + (size_t)gr1 * kC + c) = o1;
        }
    }
    __syncthreads();

    {
        float* outs = out + (size_t)kB * kN * kC + (size_t)b * kN * kC;
        #pragma unroll
        for (int i = 0; i < 16; i++) {
            int idx = tid + i * NTH;
            int row = idx >> 5, c4 = (idx & 31) << 2;
            float m1 = rowbuf[row];
            float4 v = *reinterpret_cast<const float4*>(sbp + (size_t)(n0 + row) * kC + c4);
            v.x *= m1; v.y *= m1; v.z *= m1; v.w *= m1;
            *reinterpret_cast<float4*>(outs + (size_t)(n0 + row) * kC + c4) = v;
        }
    }
}

extern "C" void kernel_launch(void* const* d_in, const int* in_sizes, int n_in,
                              void* d_out, int out_size)
{
    const float* q = (const float*)d_in[0];   // query_feature  [8,128,56,56]
    const float* s = (const float*)d_in[1];   // support_feature[8,128,56,56]
    float* out = (float*)d_out;               // [query_out | support_out]

    const size_t nf4 = SZ / 4;
    int pre_blocks = (int)((2 * nf4 + 255) / 256);
    prepass_kernel<<<pre_blocks, 256>>>(q, s);

    cudaFuncSetAttribute((const void*)fusion_mma_kernel,
                         cudaFuncAttributeMaxDynamicSharedMemorySize, SMEM_BYTES);
    dim3 grid(kN / TM, kB, NSPLIT);           // 49 x 8 x 3 = 1176 CTAs
    fusion_mma_kernel<<<grid, NTH, SMEM_BYTES>>>(q, s, out);
}

// round 14
// speedup vs baseline: 1.1545x; 1.1545x over previous
#include <cuda_runtime.h>
#include <cstdint>

// FusionFeature_Layer on GB300 — emulated-fp32 flash attention on mma.sync
// (bf16 hi/lo 3-term split), bf16 prepass + cp.async pipelined tiles.
// R14: accumulator-rotated MMA ordering + software-pipelined ldmatrix
// (breaks HMMA RAW chains; arithmetic per accumulator unchanged).
//
//   qf[b,n,c] = query.flat [b*N*C + n*C + c]
//   sf[b,c,m] = support.flat[b*C*N + c*N + m]
//   A = qf @ sf ; attn = softmax(A) ; mask = sigmoid(rowsum(A))
//   out_q = q + (attn @ qf) * mask ;  out_s = s * (1 + mask)

namespace {
constexpr int kB = 8, kC = 128, kN = 3136;   // N = 56*56 = 98*32
constexpr int TM = 64, TN = 32, NTH = 128;
constexpr int NUM_MT = kN / TN;              // 98
constexpr int BUF_BYTES = 32768;             // S(16K) + V 4x4K regions
constexpr int OFF_ROW   = 3 * BUF_BYTES;     // float rowmask1[64]
constexpr int SMEM_BYTES = OFF_ROW + 256;
constexpr size_t SZ = (size_t)kB * kN * kC;
}

// bf16 hi/lo scratch (written by prepass)
__device__ __align__(16) uint16_t g_qh[SZ];
__device__ __align__(16) uint16_t g_ql[SZ];
__device__ __align__(16) uint16_t g_sh[SZ];
__device__ __align__(16) uint16_t g_sl[SZ];

#define SWZ(b) ((b) ^ (((b) >> 3) & 0x70))

__device__ __forceinline__ uint32_t smem_to_u32(const void* p) {
    uint32_t a;
    asm("{ .reg .u64 t; cvta.to.shared.u64 t, %1; cvt.u32.u64 %0, t; }" : "=r"(a) : "l"(p));
    return a;
}
__device__ __forceinline__ void cp16(uint32_t dst, const void* src) {
    asm volatile("cp.async.cg.shared.global [%0], [%1], 16;" :: "r"(dst), "l"(src));
}
#define CP_COMMIT() asm volatile("cp.async.commit_group;" ::: "memory")
#define CP_WAIT0()  asm volatile("cp.async.wait_group 0;" ::: "memory")
#define CP_WAIT1()  asm volatile("cp.async.wait_group 1;" ::: "memory")

__device__ __forceinline__ void ldsm_x4(uint32_t r[4], uint32_t addr) {
    asm volatile("ldmatrix.sync.aligned.m8n8.x4.shared.b16 {%0,%1,%2,%3}, [%4];"
                 : "=r"(r[0]), "=r"(r[1]), "=r"(r[2]), "=r"(r[3]) : "r"(addr));
}
__device__ __forceinline__ void ldsm_x4_t(uint32_t r[4], uint32_t addr) {
    asm volatile("ldmatrix.sync.aligned.m8n8.x4.trans.shared.b16 {%0,%1,%2,%3}, [%4];"
                 : "=r"(r[0]), "=r"(r[1]), "=r"(r[2]), "=r"(r[3]) : "r"(addr));
}
__device__ __forceinline__ void mma_bf16(float (&d)[4], const uint32_t (&a)[4],
                                         uint32_t b0, uint32_t b1) {
    asm volatile("mma.sync.aligned.m16n8k16.row.col.f32.bf16.bf16.f32 "
                 "{%0,%1,%2,%3}, {%4,%5,%6,%7}, {%8,%9}, {%0,%1,%2,%3};"
                 : "+f"(d[0]), "+f"(d[1]), "+f"(d[2]), "+f"(d[3])
                 : "r"(a[0]), "r"(a[1]), "r"(a[2]), "r"(a[3]), "r"(b0), "r"(b1));
}
__device__ __forceinline__ void split2(float x, float y, uint32_t& hi, uint32_t& lo) {
    asm("cvt.rn.satfinite.bf16x2.f32 %0, %1, %2;" : "=r"(hi) : "f"(y), "f"(x));
    float rx = x - __uint_as_float(hi << 16);
    float ry = y - __uint_as_float(hi & 0xFFFF0000u);
    asm("cvt.rn.satfinite.bf16x2.f32 %0, %1, %2;" : "=r"(lo) : "f"(ry), "f"(rx));
}

// ---------------------------------------------------------------------------
__global__ __launch_bounds__(256)
void prepass_kernel(const float* __restrict__ q, const float* __restrict__ s)
{
    const size_t nf4 = SZ / 4;
    size_t i = (size_t)blockIdx.x * blockDim.x + threadIdx.x;
    const float* src;
    uint16_t *dh, *dl;
    size_t idx;
    if (i < nf4) { src = q; dh = g_qh; dl = g_ql; idx = i; }
    else         { src = s; dh = g_sh; dl = g_sl; idx = i - nf4; }
    float4 v = reinterpret_cast<const float4*>(src)[idx];
    uint32_t h0, l0, h1, l1;
    split2(v.x, v.y, h0, l0);
    split2(v.z, v.w, h1, l1);
    reinterpret_cast<uint2*>(dh)[idx] = make_uint2(h0, h1);
    reinterpret_cast<uint2*>(dl)[idx] = make_uint2(l0, l1);
}

// ---------------------------------------------------------------------------
__device__ __forceinline__ void load_tile(uint32_t bb, int tid, int b, int m0)
{
    #pragma unroll
    for (int i = 0; i < 8; i++) {                     // S: [128 c][hi64B|lo64B]
        int idx = tid + i * NTH;
        int c = idx >> 3, j = idx & 7;
        int jj = j & 3;
        const uint16_t* src = (j < 4 ? g_sh : g_sl)
            + ((size_t)(b * kC + c) * kN + m0 + jj * 8);
        uint32_t dst = bb + SWZ((uint32_t)(c * 128 + ((j >> 2) << 6) + jj * 16));
        cp16(dst, src);
    }
    #pragma unroll
    for (int i = 0; i < 8; i++) {                     // V: 4 regions [32][128B]
        int idx = tid + i * NTH;
        int rg = idx >> 8, m = (idx >> 3) & 31, j = idx & 7;
        const uint16_t* base = (rg < 2 ? g_qh : g_ql);
        const uint16_t* src = base + ((size_t)(b * kN + m0 + m) * kC) + (rg & 1) * 64 + j * 8;
        uint32_t dst = bb + 16384 + (uint32_t)rg * 4096 + SWZ((uint32_t)(m * 128 + j * 16));
        cp16(dst, src);
    }
}

// GEMM1 B-fragment group for k-step: bh(np0) bl(np0) bh(np1) bl(np1)
__device__ __forceinline__ void g1_load(uint32_t bb, int k, int rowA, int gcol, uint32_t* f)
{
    uint32_t rowb = (uint32_t)((k * 16 + rowA) * 128);
    ldsm_x4_t(f + 0,  bb + SWZ(rowb + gcol));
    ldsm_x4_t(f + 4,  bb + SWZ(rowb + 64 + gcol));
    ldsm_x4_t(f + 8,  bb + SWZ(rowb + 32 + gcol));
    ldsm_x4_t(f + 12, bb + SWZ(rowb + 96 + gcol));
}

// GEMM2 B-fragment group for (kt, npp): bh(np0) bl(np0) bh(np1) bl(np1)
__device__ __forceinline__ void g2_load(uint32_t bb, int kt, int npp, int rowA, int gcol,
                                        uint32_t* f)
{
    int np0 = npp * 2, np1 = np0 + 1;
    uint32_t vb0 = bb + 16384 + (((uint32_t)np0 >> 2) << 12);
    uint32_t vb1 = bb + 16384 + (((uint32_t)np1 >> 2) << 12);
    uint32_t off0 = SWZ((uint32_t)((kt * 16 + rowA) * 128 + ((np0 & 3) << 5) + gcol));
    uint32_t off1 = SWZ((uint32_t)((kt * 16 + rowA) * 128 + ((np1 & 3) << 5) + gcol));
    ldsm_x4_t(f + 0,  vb0 + off0);
    ldsm_x4_t(f + 4,  vb0 + 8192 + off0);
    ldsm_x4_t(f + 8,  vb1 + off1);
    ldsm_x4_t(f + 12, vb1 + 8192 + off1);
}

__global__ __launch_bounds__(NTH, 2)
void fusion_mma_kernel(const float* __restrict__ q,
                       const float* __restrict__ s,
                       float* __restrict__ out)
{
    extern __shared__ char smem[];
    const uint32_t sb = smem_to_u32(smem);
    float* rowbuf = reinterpret_cast<float*>(smem + OFF_ROW);

    const int tid  = threadIdx.x;
    const int lane = tid & 31;
    const int wid  = tid >> 5;
    const int R    = wid * 16;
    const int rowA = lane & 15;
    const int gcol = (lane >> 4) << 4;

    const int b  = blockIdx.y;
    const int n0 = blockIdx.x * TM;
    const float* __restrict__ qb  = q + (size_t)b * kN * kC;
    const float* __restrict__ sbp = s + (size_t)b * kN * kC;

    // ---- Stage Q tile (bf16 hi/lo from scratch), hoist A-fragments ----
    #pragma unroll
    for (int i = 0; i < 16; i++) {
        int idx = tid + i * NTH;
        int hl = idx >> 10;
        int r = (idx >> 4) & 63, j = idx & 15;
        int ch = j >> 3, jj = j & 7;
        const uint16_t* base = hl ? g_ql : g_qh;
        const uint16_t* src = base + ((size_t)(b * kN + n0 + r) * kC) + ch * 64 + jj * 8;
        uint32_t dst = sb + (uint32_t)hl * 16384 + (uint32_t)ch * 8192
                     + SWZ((uint32_t)(r * 128 + jj * 16));
        cp16(dst, src);
    }
    CP_COMMIT(); CP_WAIT0(); __syncthreads();

    uint32_t qah[8][4], qal[8][4];
    #pragma unroll
    for (int k = 0; k < 8; k++) {
        uint32_t inner = SWZ((uint32_t)((R + rowA) * 128 + ((k & 3) << 5) + gcol));
        ldsm_x4(qah[k], sb + ((uint32_t)(k >> 2) << 13) + inner);
        ldsm_x4(qal[k], sb + 16384 + ((uint32_t)(k >> 2) << 13) + inner);
    }
    __syncthreads();

    float oacc[16][4];
    #pragma unroll
    for (int i = 0; i < 16; i++)
        #pragma unroll
        for (int j = 0; j < 4; j++) oacc[i][j] = 0.f;
    float raw0 = 0.f, raw1 = 0.f, es0 = 0.f, es1 = 0.f;

    load_tile(sb,             tid, b, 0);  CP_COMMIT();
    load_tile(sb + BUF_BYTES, tid, b, TN); CP_COMMIT();

    uint32_t bufc = sb;
    uint32_t bufp = sb + 2u * BUF_BYTES;

    #pragma unroll 1
    for (int mt = 0; mt < NUM_MT; mt++) {
        CP_WAIT1();
        __syncthreads();
        if (mt + 2 < NUM_MT) load_tile(bufp, tid, b, (mt + 2) * TN);
        CP_COMMIT();

        const uint32_t bb = bufc;

        // ---- GEMM1: S(16x32/warp) = Q(16x128) @ Sf(128x32) ----
        // 12 MMAs per k-step in accumulator-rotated order (reuse distance 4);
        // B-fragments double-buffered one k-step ahead.
        float sacc[4][4];
        #pragma unroll
        for (int i = 0; i < 4; i++)
            #pragma unroll
            for (int j = 0; j < 4; j++) sacc[i][j] = 0.f;

        uint32_t f1[2][16];
        g1_load(bb, 0, rowA, gcol, f1[0]);
        #pragma unroll
        for (int k = 0; k < 8; k++) {
            if (k < 7) g1_load(bb, k + 1, rowA, gcol, f1[(k + 1) & 1]);
            const uint32_t* f = f1[k & 1];
            // hh
            mma_bf16(sacc[0], qah[k], f[0],  f[1]);
            mma_bf16(sacc[1], qah[k], f[2],  f[3]);
            mma_bf16(sacc[2], qah[k], f[8],  f[9]);
            mma_bf16(sacc[3], qah[k], f[10], f[11]);
            // hl
            mma_bf16(sacc[0], qah[k], f[4],  f[5]);
            mma_bf16(sacc[1], qah[k], f[6],  f[7]);
            mma_bf16(sacc[2], qah[k], f[12], f[13]);
            mma_bf16(sacc[3], qah[k], f[14], f[15]);
            // lh
            mma_bf16(sacc[0], qal[k], f[0],  f[1]);
            mma_bf16(sacc[1], qal[k], f[2],  f[3]);
            mma_bf16(sacc[2], qal[k], f[8],  f[9]);
            mma_bf16(sacc[3], qal[k], f[10], f[11]);
        }

        // prefetch GEMM2's first V fragment group under the exp/pack math
        uint32_t f2[2][16];
        g2_load(bb, 0, 0, rowA, gcol, f2[0]);

        // ---- exp + row partials; pack P into GEMM2 A-fragments ----
        uint32_t pah[2][4], pal[2][4];
        #pragma unroll
        for (int nt = 0; nt < 4; nt++) {
            float v0 = sacc[nt][0], v1 = sacc[nt][1], v2 = sacc[nt][2], v3 = sacc[nt][3];
            raw0 += v0 + v1;  raw1 += v2 + v3;
            float e0 = __expf(v0), e1 = __expf(v1), e2 = __expf(v2), e3 = __expf(v3);
            es0 += e0 + e1;   es1 += e2 + e3;
            int kt = nt >> 1, o = (nt & 1) << 1;
            split2(e0, e1, pah[kt][o],     pal[kt][o]);
            split2(e2, e3, pah[kt][o + 1], pal[kt][o + 1]);
        }

        // ---- GEMM2: O(16x128/warp) += P(16x32) @ V(32x128) ----
        // 8 groups of (kt, npp); 12 MMAs each, rotated over 4 accumulators;
        // fragment groups double-buffered one group ahead.
        #pragma unroll
        for (int g = 0; g < 8; g++) {
            const int kt = g >> 2, npp = g & 3;
            if (g < 7) g2_load(bb, (g + 1) >> 2, (g + 1) & 3, rowA, gcol, f2[(g + 1) & 1]);
            const uint32_t* f = f2[g & 1];
            float (*o)[4] = &oacc[npp * 4];
            // hh
            mma_bf16(o[0], pah[kt], f[0],  f[1]);
            mma_bf16(o[1], pah[kt], f[2],  f[3]);
            mma_bf16(o[2], pah[kt], f[8],  f[9]);
            mma_bf16(o[3], pah[kt], f[10], f[11]);
            // hl
            mma_bf16(o[0], pah[kt], f[4],  f[5]);
            mma_bf16(o[1], pah[kt], f[6],  f[7]);
            mma_bf16(o[2], pah[kt], f[12], f[13]);
            mma_bf16(o[3], pah[kt], f[14], f[15]);
            // lh
            mma_bf16(o[0], pal[kt], f[0],  f[1]);
            mma_bf16(o[1], pal[kt], f[2],  f[3]);
            mma_bf16(o[2], pal[kt], f[8],  f[9]);
            mma_bf16(o[3], pal[kt], f[10], f[11]);
        }

        bufc = (bufc == sb + 2u * BUF_BYTES) ? sb : bufc + BUF_BYTES;
        bufp = (bufp == sb + 2u * BUF_BYTES) ? sb : bufp + BUF_BYTES;
    }

    // ---- quad-reduce row partials (rows gr0 = lane/4, gr1 = gr0+8) ----
    #pragma unroll
    for (int off = 1; off < 4; off <<= 1) {
        raw0 += __shfl_xor_sync(0xffffffffu, raw0, off);
        raw1 += __shfl_xor_sync(0xffffffffu, raw1, off);
        es0  += __shfl_xor_sync(0xffffffffu, es0,  off);
        es1  += __shfl_xor_sync(0xffffffffu, es1,  off);
    }
    float mask0 = 1.f / (1.f + __expf(-raw0));
    float mask1 = 1.f / (1.f + __expf(-raw1));
    float sc0 = mask0 / es0, sc1 = mask1 / es1;
    if ((lane & 3) == 0) {
        rowbuf[R + (lane >> 2)]     = 1.f + mask0;
        rowbuf[R + (lane >> 2) + 8] = 1.f + mask1;
    }

    // ---- query output: out_q = q + O * scale ----
    {
        float* outq = out + (size_t)b * kN * kC;
        int gr0 = n0 + R + (lane >> 2);
        int gr1 = gr0 + 8;
        #pragma unroll
        for (int nt = 0; nt < 16; nt++) {
            int c = nt * 8 + (lane & 3) * 2;
            float2 q0 = *reinterpret_cast<const float2*>(qb + (size_t)gr0 * kC + c);
            float2 q1 = *reinterpret_cast<const float2*>(qb + (size_t)gr1 * kC + c);
            float2 o0, o1;
            o0.x = fmaf(oacc[nt][0], sc0, q0.x);
            o0.y = fmaf(oacc[nt][1], sc0, q0.y);
            o1.x = fmaf(oacc[nt][2], sc1, q1.x);
            o1.y = fmaf(oacc[nt][3], sc1, q1.y);
            *reinterpret_cast<float2*>(outq + (size_t)gr0 * kC + c) = o0;
            *reinterpret_cast<float2*>(outq + (size_t)gr1 * kC + c) = o1;
        }
    }
    __syncthreads();

    // ---- support output: out_s = s * (1 + mask[row]) ----
    {
        float* outs = out + (size_t)kB * kN * kC + (size_t)b * kN * kC;
        #pragma unroll
        for (int i = 0; i < 16; i++) {
            int idx = tid + i * NTH;
            int row = idx >> 5, c4 = (idx & 31) << 2;
            float m1 = rowbuf[row];
            float4 v = *reinterpret_cast<const float4*>(sbp + (size_t)(n0 + row) * kC + c4);
            v.x *= m1; v.y *= m1; v.z *= m1; v.w *= m1;
            *reinterpret_cast<float4*>(outs + (size_t)(n0 + row) * kC + c4) = v;
        }
    }
}

extern "C" void kernel_launch(void* const* d_in, const int* in_sizes, int n_in,
                              void* d_out, int out_size)
{
    const float* q = (const float*)d_in[0];   // query_feature  [8,128,56,56]
    const float* s = (const float*)d_in[1];   // support_feature[8,128,56,56]
    float* out = (float*)d_out;               // [query_out | support_out]

    const size_t nf4 = SZ / 4;
    int pre_blocks = (int)((2 * nf4 + 255) / 256);
    prepass_kernel<<<pre_blocks, 256>>>(q, s);

    cudaFuncSetAttribute((const void*)fusion_mma_kernel,
                         cudaFuncAttributeMaxDynamicSharedMemorySize, SMEM_BYTES);
    dim3 grid(kN / TM, kB);                   // 49 x 8 = 392 CTAs
    fusion_mma_kernel<<<grid, NTH, SMEM_BYTES>>>(q, s, out);
}

// round 15
// speedup vs baseline: 1.4294x; 1.2381x over previous
#include <cuda_runtime.h>
#include <cstdint>

// FusionFeature_Layer on GB300 — emulated-fp32 flash attention on mma.sync
// (bf16 hi/lo 3-term split), bf16 prepass + cp.async pipelined tiles.
// R15 = R12 structure (register-neutral) + interleaved accumulator issue
// order inside each MMA group (breaks RAW chains, same arithmetic order
// per accumulator -> bitwise-identical output).
//
//   qf[b,n,c] = query.flat [b*N*C + n*C + c]
//   sf[b,c,m] = support.flat[b*C*N + c*N + m]
//   A = qf @ sf ; attn = softmax(A) ; mask = sigmoid(rowsum(A))
//   out_q = q + (attn @ qf) * mask ;  out_s = s * (1 + mask)

namespace {
constexpr int kB = 8, kC = 128, kN = 3136;   // N = 56*56 = 98*32
constexpr int TM = 64, TN = 32, NTH = 128;
constexpr int NUM_MT = kN / TN;              // 98
constexpr int BUF_BYTES = 32768;             // S(16K) + V 4x4K regions
constexpr int OFF_ROW   = 3 * BUF_BYTES;     // float rowmask1[64]
constexpr int SMEM_BYTES = OFF_ROW + 256;
constexpr size_t SZ = (size_t)kB * kN * kC;
}

// bf16 hi/lo scratch (written by prepass)
__device__ __align__(16) uint16_t g_qh[SZ];
__device__ __align__(16) uint16_t g_ql[SZ];
__device__ __align__(16) uint16_t g_sh[SZ];
__device__ __align__(16) uint16_t g_sl[SZ];

#define SWZ(b) ((b) ^ (((b) >> 3) & 0x70))

__device__ __forceinline__ uint32_t smem_to_u32(const void* p) {
    uint32_t a;
    asm("{ .reg .u64 t; cvta.to.shared.u64 t, %1; cvt.u32.u64 %0, t; }" : "=r"(a) : "l"(p));
    return a;
}
__device__ __forceinline__ void cp16(uint32_t dst, const void* src) {
    asm volatile("cp.async.cg.shared.global [%0], [%1], 16;" :: "r"(dst), "l"(src));
}
#define CP_COMMIT() asm volatile("cp.async.commit_group;" ::: "memory")
#define CP_WAIT0()  asm volatile("cp.async.wait_group 0;" ::: "memory")
#define CP_WAIT1()  asm volatile("cp.async.wait_group 1;" ::: "memory")

__device__ __forceinline__ void ldsm_x4(uint32_t r[4], uint32_t addr) {
    asm volatile("ldmatrix.sync.aligned.m8n8.x4.shared.b16 {%0,%1,%2,%3}, [%4];"
                 : "=r"(r[0]), "=r"(r[1]), "=r"(r[2]), "=r"(r[3]) : "r"(addr));
}
__device__ __forceinline__ void ldsm_x4_t(uint32_t r[4], uint32_t addr) {
    asm volatile("ldmatrix.sync.aligned.m8n8.x4.trans.shared.b16 {%0,%1,%2,%3}, [%4];"
                 : "=r"(r[0]), "=r"(r[1]), "=r"(r[2]), "=r"(r[3]) : "r"(addr));
}
__device__ __forceinline__ void mma_bf16(float (&d)[4], const uint32_t (&a)[4],
                                         uint32_t b0, uint32_t b1) {
    asm volatile("mma.sync.aligned.m16n8k16.row.col.f32.bf16.bf16.f32 "
                 "{%0,%1,%2,%3}, {%4,%5,%6,%7}, {%8,%9}, {%0,%1,%2,%3};"
                 : "+f"(d[0]), "+f"(d[1]), "+f"(d[2]), "+f"(d[3])
                 : "r"(a[0]), "r"(a[1]), "r"(a[2]), "r"(a[3]), "r"(b0), "r"(b1));
}
__device__ __forceinline__ void split2(float x, float y, uint32_t& hi, uint32_t& lo) {
    asm("cvt.rn.satfinite.bf16x2.f32 %0, %1, %2;" : "=r"(hi) : "f"(y), "f"(x));
    float rx = x - __uint_as_float(hi << 16);
    float ry = y - __uint_as_float(hi & 0xFFFF0000u);
    asm("cvt.rn.satfinite.bf16x2.f32 %0, %1, %2;" : "=r"(lo) : "f"(ry), "f"(rx));
}

// ---------------------------------------------------------------------------
__global__ __launch_bounds__(256)
void prepass_kernel(const float* __restrict__ q, const float* __restrict__ s)
{
    const size_t nf4 = SZ / 4;
    size_t i = (size_t)blockIdx.x * blockDim.x + threadIdx.x;
    const float* src;
    uint16_t *dh, *dl;
    size_t idx;
    if (i < nf4) { src = q; dh = g_qh; dl = g_ql; idx = i; }
    else         { src = s; dh = g_sh; dl = g_sl; idx = i - nf4; }
    float4 v = reinterpret_cast<const float4*>(src)[idx];
    uint32_t h0, l0, h1, l1;
    split2(v.x, v.y, h0, l0);
    split2(v.z, v.w, h1, l1);
    reinterpret_cast<uint2*>(dh)[idx] = make_uint2(h0, h1);
    reinterpret_cast<uint2*>(dl)[idx] = make_uint2(l0, l1);
}

// ---------------------------------------------------------------------------
__device__ __forceinline__ void load_tile(uint32_t bb, int tid, int b, int m0)
{
    #pragma unroll
    for (int i = 0; i < 8; i++) {                     // S: [128 c][hi64B|lo64B]
        int idx = tid + i * NTH;
        int c = idx >> 3, j = idx & 7;
        int jj = j & 3;
        const uint16_t* src = (j < 4 ? g_sh : g_sl)
            + ((size_t)(b * kC + c) * kN + m0 + jj * 8);
        uint32_t dst = bb + SWZ((uint32_t)(c * 128 + ((j >> 2) << 6) + jj * 16));
        cp16(dst, src);
    }
    #pragma unroll
    for (int i = 0; i < 8; i++) {                     // V: 4 regions [32][128B]
        int idx = tid + i * NTH;
        int rg = idx >> 8, m = (idx >> 3) & 31, j = idx & 7;
        const uint16_t* base = (rg < 2 ? g_qh : g_ql);
        const uint16_t* src = base + ((size_t)(b * kN + m0 + m) * kC) + (rg & 1) * 64 + j * 8;
        uint32_t dst = bb + 16384 + (uint32_t)rg * 4096 + SWZ((uint32_t)(m * 128 + j * 16));
        cp16(dst, src);
    }
}

__global__ __launch_bounds__(NTH, 2)
void fusion_mma_kernel(const float* __restrict__ q,
                       const float* __restrict__ s,
                       float* __restrict__ out)
{
    extern __shared__ char smem[];
    const uint32_t sb = smem_to_u32(smem);
    float* rowbuf = reinterpret_cast<float*>(smem + OFF_ROW);

    const int tid  = threadIdx.x;
    const int lane = tid & 31;
    const int wid  = tid >> 5;
    const int R    = wid * 16;
    const int rowA = lane & 15;
    const int gcol = (lane >> 4) << 4;

    const int b  = blockIdx.y;
    const int n0 = blockIdx.x * TM;
    const float* __restrict__ qb  = q + (size_t)b * kN * kC;
    const float* __restrict__ sbp = s + (size_t)b * kN * kC;

    // ---- Stage Q tile (bf16 hi/lo from scratch), hoist A-fragments ----
    #pragma unroll
    for (int i = 0; i < 16; i++) {
        int idx = tid + i * NTH;
        int hl = idx >> 10;
        int r = (idx >> 4) & 63, j = idx & 15;
        int ch = j >> 3, jj = j & 7;
        const uint16_t* base = hl ? g_ql : g_qh;
        const uint16_t* src = base + ((size_t)(b * kN + n0 + r) * kC) + ch * 64 + jj * 8;
        uint32_t dst = sb + (uint32_t)hl * 16384 + (uint32_t)ch * 8192
                     + SWZ((uint32_t)(r * 128 + jj * 16));
        cp16(dst, src);
    }
    CP_COMMIT(); CP_WAIT0(); __syncthreads();

    uint32_t qah[8][4], qal[8][4];
    #pragma unroll
    for (int k = 0; k < 8; k++) {
        uint32_t inner = SWZ((uint32_t)((R + rowA) * 128 + ((k & 3) << 5) + gcol));
        ldsm_x4(qah[k], sb + ((uint32_t)(k >> 2) << 13) + inner);
        ldsm_x4(qal[k], sb + 16384 + ((uint32_t)(k >> 2) << 13) + inner);
    }
    __syncthreads();

    float oacc[16][4];
    #pragma unroll
    for (int i = 0; i < 16; i++)
        #pragma unroll
        for (int j = 0; j < 4; j++) oacc[i][j] = 0.f;
    float raw0 = 0.f, raw1 = 0.f, es0 = 0.f, es1 = 0.f;

    load_tile(sb,             tid, b, 0);  CP_COMMIT();
    load_tile(sb + BUF_BYTES, tid, b, TN); CP_COMMIT();

    uint32_t bufc = sb;
    uint32_t bufp = sb + 2u * BUF_BYTES;

    #pragma unroll 1
    for (int mt = 0; mt < NUM_MT; mt++) {
        CP_WAIT1();
        __syncthreads();
        if (mt + 2 < NUM_MT) load_tile(bufp, tid, b, (mt + 2) * TN);
        CP_COMMIT();

        const uint32_t bb = bufc;

        // ---- GEMM1: S(16x32/warp) = Q(16x128) @ Sf(128x32), 3-term ----
        // Interleaved accumulator order (distance-2), same math per acc.
        float sacc[4][4];
        #pragma unroll
        for (int i = 0; i < 4; i++)
            #pragma unroll
            for (int j = 0; j < 4; j++) sacc[i][j] = 0.f;

        #pragma unroll
        for (int k = 0; k < 8; k++) {
            uint32_t rowb = (uint32_t)((k * 16 + rowA) * 128);
            #pragma unroll
            for (int np = 0; np < 2; np++) {
                uint32_t bh[4], bl[4];
                ldsm_x4_t(bh, bb + SWZ(rowb + ((uint32_t)np << 5) + gcol));
                ldsm_x4_t(bl, bb + SWZ(rowb + 64 + ((uint32_t)np << 5) + gcol));
                float (&sA)[4] = sacc[2*np];
                float (&sB)[4] = sacc[2*np+1];
                mma_bf16(sA, qah[k], bh[0], bh[1]);   // hh
                mma_bf16(sB, qah[k], bh[2], bh[3]);   // hh
                mma_bf16(sA, qah[k], bl[0], bl[1]);   // hl
                mma_bf16(sB, qah[k], bl[2], bl[3]);   // hl
                mma_bf16(sA, qal[k], bh[0], bh[1]);   // lh
                mma_bf16(sB, qal[k], bh[2], bh[3]);   // lh
            }
        }

        // ---- exp + row partials; pack P into GEMM2 A-fragments ----
        uint32_t pah[2][4], pal[2][4];
        #pragma unroll
        for (int nt = 0; nt < 4; nt++) {
            float v0 = sacc[nt][0], v1 = sacc[nt][1], v2 = sacc[nt][2], v3 = sacc[nt][3];
            raw0 += v0 + v1;  raw1 += v2 + v3;
            float e0 = __expf(v0), e1 = __expf(v1), e2 = __expf(v2), e3 = __expf(v3);
            es0 += e0 + e1;   es1 += e2 + e3;
            int kt = nt >> 1, o = (nt & 1) << 1;
            split2(e0, e1, pah[kt][o],     pal[kt][o]);
            split2(e2, e3, pah[kt][o + 1], pal[kt][o + 1]);
        }

        // ---- GEMM2: O(16x128/warp) += P(16x32) @ V(32x128), 3-term ----
        // Interleaved accumulator order (distance-2), same math per acc.
        #pragma unroll
        for (int np = 0; np < 8; np++) {
            uint32_t vb = bb + 16384 + (((uint32_t)np >> 2) << 12);
            #pragma unroll
            for (int kt = 0; kt < 2; kt++) {
                uint32_t bh[4], bl[4];
                uint32_t off = SWZ((uint32_t)((kt * 16 + rowA) * 128 + ((np & 3) << 5) + gcol));
                ldsm_x4_t(bh, vb + off);
                ldsm_x4_t(bl, vb + 8192 + off);
                float (&oA)[4] = oacc[2*np];
                float (&oB)[4] = oacc[2*np+1];
                mma_bf16(oA, pah[kt], bh[0], bh[1]);  // hh
                mma_bf16(oB, pah[kt], bh[2], bh[3]);  // hh
                mma_bf16(oA, pah[kt], bl[0], bl[1]);  // hl
                mma_bf16(oB, pah[kt], bl[2], bl[3]);  // hl
                mma_bf16(oA, pal[kt], bh[0], bh[1]);  // lh
                mma_bf16(oB, pal[kt], bh[2], bh[3]);  // lh
            }
        }

        bufc = (bufc == sb + 2u * BUF_BYTES) ? sb : bufc + BUF_BYTES;
        bufp = (bufp == sb + 2u * BUF_BYTES) ? sb : bufp + BUF_BYTES;
    }

    // ---- quad-reduce row partials (rows gr0 = lane/4, gr1 = gr0+8) ----
    #pragma unroll
    for (int off = 1; off < 4; off <<= 1) {
        raw0 += __shfl_xor_sync(0xffffffffu, raw0, off);
        raw1 += __shfl_xor_sync(0xffffffffu, raw1, off);
        es0  += __shfl_xor_sync(0xffffffffu, es0,  off);
        es1  += __shfl_xor_sync(0xffffffffu, es1,  off);
    }
    float mask0 = 1.f / (1.f + __expf(-raw0));
    float mask1 = 1.f / (1.f + __expf(-raw1));
    float sc0 = mask0 / es0, sc1 = mask1 / es1;
    if ((lane & 3) == 0) {
        rowbuf[R + (lane >> 2)]     = 1.f + mask0;
        rowbuf[R + (lane >> 2) + 8] = 1.f + mask1;
    }

    // ---- query output: out_q = q + O * scale ----
    {
        float* outq = out + (size_t)b * kN * kC;
        int gr0 = n0 + R + (lane >> 2);
        int gr1 = gr0 + 8;
        #pragma unroll
        for (int nt = 0; nt < 16; nt++) {
            int c = nt * 8 + (lane & 3) * 2;
            float2 q0 = *reinterpret_cast<const float2*>(qb + (size_t)gr0 * kC + c);
            float2 q1 = *reinterpret_cast<const float2*>(qb + (size_t)gr1 * kC + c);
            float2 o0, o1;
            o0.x = fmaf(oacc[nt][0], sc0, q0.x);
            o0.y = fmaf(oacc[nt][1], sc0, q0.y);
            o1.x = fmaf(oacc[nt][2], sc1, q1.x);
            o1.y = fmaf(oacc[nt][3], sc1, q1.y);
            *reinterpret_cast<float2*>(outq + (size_t)gr0 * kC + c) = o0;
            *reinterpret_cast<float2*>(outq + (size_t)gr1 * kC + c) = o1;
        }
    }
    __syncthreads();

    // ---- support output: out_s = s * (1 + mask[row]) ----
    {
        float* outs = out + (size_t)kB * kN * kC + (size_t)b * kN * kC;
        #pragma unroll
        for (int i = 0; i < 16; i++) {
            int idx = tid + i * NTH;
            int row = idx >> 5, c4 = (idx & 31) << 2;
            float m1 = rowbuf[row];
            float4 v = *reinterpret_cast<const float4*>(sbp + (size_t)(n0 + row) * kC + c4);
            v.x *= m1; v.y *= m1; v.z *= m1; v.w *= m1;
            *reinterpret_cast<float4*>(outs + (size_t)(n0 + row) * kC + c4) = v;
        }
    }
}

extern "C" void kernel_launch(void* const* d_in, const int* in_sizes, int n_in,
                              void* d_out, int out_size)
{
    const float* q = (const float*)d_in[0];   // query_feature  [8,128,56,56]
    const float* s = (const float*)d_in[1];   // support_feature[8,128,56,56]
    float* out = (float*)d_out;               // [query_out | support_out]

    const size_t nf4 = SZ / 4;
    int pre_blocks = (int)((2 * nf4 + 255) / 256);
    prepass_kernel<<<pre_blocks, 256>>>(q, s);

    cudaFuncSetAttribute((const void*)fusion_mma_kernel,
                         cudaFuncAttributeMaxDynamicSharedMemorySize, SMEM_BYTES);
    dim3 grid(kN / TM, kB);                   // 49 x 8 = 392 CTAs
    fusion_mma_kernel<<<grid, NTH, SMEM_BYTES>>>(q, s, out);
}